// round 1
// baseline (speedup 1.0000x reference)
#include <cuda_runtime.h>
#include <cstdint>

// Problem constants (from reference)
#define NTOK 2048
#define DDIM 512
#define HDIM 2048
#define GNUM 4
#define EPG  4
#define ENUM 16
#define GTP_THR 0.9f
#define TP_THR  0.9f
#define SCALE_W 0.5f   // 1/sqrt(4)

// Scratch (static device arrays; fixed-stride buckets, no allocation)
__device__ float d_tw[NTOK * ENUM];
__device__ int   d_slot[NTOK * ENUM];
__device__ int   d_bucket_tok[ENUM * NTOK];
__device__ float d_bucket_w[ENUM * NTOK];
__device__ int   d_counts[ENUM];
__device__ float d_h[(size_t)ENUM * NTOK * HDIM];        // 256 MB
__device__ float d_partial[(size_t)ENUM * NTOK * DDIM];  // 64 MB

// ---------------------------------------------------------------------------
// Routing: one warp per token. 20 dots of length 512, then exact top-2 logic.
// ---------------------------------------------------------------------------
__device__ __forceinline__ void top2norm(const float* logit, float thr, float* w) {
    // softmax over 4
    float m = logit[0];
    #pragma unroll
    for (int i = 1; i < 4; i++) m = fmaxf(m, logit[i]);
    float p[4], s = 0.f;
    #pragma unroll
    for (int i = 0; i < 4; i++) { p[i] = expf(logit[i] - m); s += p[i]; }
    #pragma unroll
    for (int i = 0; i < 4; i++) p[i] /= s;
    // top-2, stable (first index wins ties) -> matches argsort(-p) stable
    int i0 = 0; float b0 = p[0];
    #pragma unroll
    for (int i = 1; i < 4; i++) if (p[i] > b0) { b0 = p[i]; i0 = i; }
    int i1 = -1; float b1 = -1.f;
    #pragma unroll
    for (int i = 0; i < 4; i++) if (i != i0 && p[i] > b1) { b1 = p[i]; i1 = i; }
    bool act1 = (b0 + b1) <= thr;         // cumsum<=thr; first always active
    float mp1 = act1 ? b1 : 0.f;
    float den = b0 + mp1 + 1e-9f;
    #pragma unroll
    for (int i = 0; i < 4; i++) w[i] = 0.f;
    w[i0] = b0 / den;
    w[i1] = mp1 / den;
}

__global__ __launch_bounds__(256) void routing_kernel(
    const float* __restrict__ x, const float* __restrict__ Wr,
    const float* __restrict__ br, const float* __restrict__ Wg,
    const float* __restrict__ bg)
{
    int wid = threadIdx.x >> 5, lane = threadIdx.x & 31;
    int n = blockIdx.x * 8 + wid;
    const float* xr = x + (size_t)n * DDIM;
    float xv[16];
    #pragma unroll
    for (int i = 0; i < 16; i++) xv[i] = xr[lane + 32 * i];

    float acc[20];
    #pragma unroll
    for (int g = 0; g < 4; g++) {
        float s = 0.f;
        #pragma unroll
        for (int i = 0; i < 16; i++) s += xv[i] * Wr[(lane + 32 * i) * 4 + g];
        acc[g] = s;
    }
    #pragma unroll
    for (int g = 0; g < 4; g++) {
        #pragma unroll
        for (int e = 0; e < 4; e++) {
            float s = 0.f;
            const float* wgp = Wg + (size_t)g * DDIM * EPG + e;
            #pragma unroll
            for (int i = 0; i < 16; i++) s += xv[i] * wgp[(lane + 32 * i) * 4];
            acc[4 + g * 4 + e] = s;
        }
    }
    #pragma unroll
    for (int o = 16; o; o >>= 1) {
        #pragma unroll
        for (int j = 0; j < 20; j++) acc[j] += __shfl_xor_sync(0xffffffffu, acc[j], o);
    }

    if (lane == 0) {
        float gl[4];
        #pragma unroll
        for (int g = 0; g < 4; g++) gl[g] = acc[g] + br[g];
        float wgrp[4];
        top2norm(gl, GTP_THR, wgrp);
        #pragma unroll
        for (int g = 0; g < 4; g++) {
            float el[4];
            #pragma unroll
            for (int e = 0; e < 4; e++) el[e] = acc[4 + g * 4 + e] + bg[g * 4 + e];
            float wexp[4];
            top2norm(el, TP_THR, wexp);
            #pragma unroll
            for (int e = 0; e < 4; e++) {
                d_tw[n * ENUM + g * 4 + e] = wgrp[g] * wexp[e] * SCALE_W;
                d_slot[n * ENUM + g * 4 + e] = -1;
            }
        }
    }
}

// ---------------------------------------------------------------------------
// Deterministic bucket build: one block per expert, block-wide scan.
// ---------------------------------------------------------------------------
__global__ __launch_bounds__(256) void build_buckets() {
    int e = blockIdx.x;
    int t = threadIdx.x;
    __shared__ int sc[256];
    int base = t * 8;
    float wv[8];
    int flags = 0, cnt = 0;
    #pragma unroll
    for (int j = 0; j < 8; j++) {
        float v = d_tw[(base + j) * ENUM + e];
        wv[j] = v;
        if (v > 0.f) { flags |= 1 << j; cnt++; }
    }
    sc[t] = cnt;
    __syncthreads();
    for (int off = 1; off < 256; off <<= 1) {
        int v = sc[t];
        int add = (t >= off) ? sc[t - off] : 0;
        __syncthreads();
        sc[t] = v + add;
        __syncthreads();
    }
    int pos = sc[t] - cnt;
    #pragma unroll
    for (int j = 0; j < 8; j++) {
        if ((flags >> j) & 1) {
            int n = base + j;
            d_bucket_tok[e * NTOK + pos] = n;
            d_bucket_w[e * NTOK + pos] = wv[j];
            d_slot[n * ENUM + e] = pos;
            pos++;
        }
    }
    if (t == 255) d_counts[e] = sc[255];
}

// ---------------------------------------------------------------------------
// Pass 1: per expert, gathered rows: h = silu(x@W1) * (x@W3). Tiles 128x64, K=16.
// ---------------------------------------------------------------------------
#define TM 128
#define TN 64
#define TK 16

__global__ __launch_bounds__(256) void ffn_up(
    const float* __restrict__ x, const float* __restrict__ W1,
    const float* __restrict__ W3)
{
    int e = blockIdx.z;
    int cnt = d_counts[e];
    int m0 = blockIdx.y * TM;
    if (m0 >= cnt) return;
    int n0 = blockIdx.x * TN;

    __shared__ float As[TK][TM];
    __shared__ float B1s[TK][TN];
    __shared__ float B3s[TK][TN];

    int tid = threadIdx.x;
    int tx = tid & 15, ty = tid >> 4;

    // A-load mapping: 2 threads per row, 8 consecutive k each
    int lrow = tid >> 1;
    int lk = (tid & 1) * 8;
    int grow = m0 + lrow;
    int gi = grow < cnt ? grow : cnt - 1;
    int tok = d_bucket_tok[e * NTOK + gi];
    const float* xrow = x + (size_t)tok * DDIM + lk;

    // B-load mapping: row kb = tid>>4 (0..15), 4 consecutive cols
    int kb = tid >> 4, cb = (tid & 15) * 4;
    const float* w1p = W1 + (size_t)e * DDIM * HDIM + (size_t)kb * HDIM + n0 + cb;
    const float* w3p = W3 + (size_t)e * DDIM * HDIM + (size_t)kb * HDIM + n0 + cb;

    float c1[8][4], c2[8][4];
    #pragma unroll
    for (int i = 0; i < 8; i++)
        #pragma unroll
        for (int j = 0; j < 4; j++) { c1[i][j] = 0.f; c2[i][j] = 0.f; }

    for (int k0 = 0; k0 < DDIM; k0 += TK) {
        #pragma unroll
        for (int j = 0; j < 8; j++) As[lk + j][lrow] = xrow[k0 + j];
        float4 b1 = *(const float4*)(w1p + (size_t)k0 * HDIM);
        float4 b3 = *(const float4*)(w3p + (size_t)k0 * HDIM);
        *(float4*)&B1s[kb][cb] = b1;
        *(float4*)&B3s[kb][cb] = b3;
        __syncthreads();
        #pragma unroll
        for (int kk = 0; kk < TK; kk++) {
            float4 A0 = *(float4*)&As[kk][ty * 8];
            float4 A1 = *(float4*)&As[kk][ty * 8 + 4];
            float a[8] = {A0.x, A0.y, A0.z, A0.w, A1.x, A1.y, A1.z, A1.w};
            float4 bb1 = *(float4*)&B1s[kk][tx * 4];
            float4 bb3 = *(float4*)&B3s[kk][tx * 4];
            float bv1[4] = {bb1.x, bb1.y, bb1.z, bb1.w};
            float bv3[4] = {bb3.x, bb3.y, bb3.z, bb3.w};
            #pragma unroll
            for (int mi = 0; mi < 8; mi++)
                #pragma unroll
                for (int ni = 0; ni < 4; ni++) {
                    c1[mi][ni] += a[mi] * bv1[ni];
                    c2[mi][ni] += a[mi] * bv3[ni];
                }
        }
        __syncthreads();
    }

    float* hp = d_h + ((size_t)e * NTOK + m0) * HDIM + n0;
    #pragma unroll
    for (int mi = 0; mi < 8; mi++) {
        int r = ty * 8 + mi;
        #pragma unroll
        for (int ni = 0; ni < 4; ni++) {
            float a = c1[mi][ni];
            float hv = (a / (1.f + __expf(-a))) * c2[mi][ni];
            hp[(size_t)r * HDIM + tx * 4 + ni] = hv;
        }
    }
}

// ---------------------------------------------------------------------------
// Pass 2: partial = tw_row * (h @ W2). Tiles 128x64, K=2048 in chunks of 16.
// ---------------------------------------------------------------------------
__global__ __launch_bounds__(256) void ffn_down(const float* __restrict__ W2)
{
    int e = blockIdx.z;
    int cnt = d_counts[e];
    int m0 = blockIdx.y * TM;
    if (m0 >= cnt) return;
    int n0 = blockIdx.x * TN;

    __shared__ float As[TK][TM];
    __shared__ float Bs[TK][TN];

    int tid = threadIdx.x;
    int tx = tid & 15, ty = tid >> 4;

    int lrow = tid >> 1;
    int lk = (tid & 1) * 8;
    const float* hrow = d_h + ((size_t)e * NTOK + m0 + lrow) * HDIM + lk;

    int kb = tid >> 4, cb = (tid & 15) * 4;
    const float* w2p = W2 + (size_t)e * HDIM * DDIM + (size_t)kb * DDIM + n0 + cb;

    float c[8][4];
    #pragma unroll
    for (int i = 0; i < 8; i++)
        #pragma unroll
        for (int j = 0; j < 4; j++) c[i][j] = 0.f;

    for (int k0 = 0; k0 < HDIM; k0 += TK) {
        #pragma unroll
        for (int j = 0; j < 8; j++) As[lk + j][lrow] = hrow[k0 + j];
        float4 b = *(const float4*)(w2p + (size_t)k0 * DDIM);
        *(float4*)&Bs[kb][cb] = b;
        __syncthreads();
        #pragma unroll
        for (int kk = 0; kk < TK; kk++) {
            float4 A0 = *(float4*)&As[kk][ty * 8];
            float4 A1 = *(float4*)&As[kk][ty * 8 + 4];
            float a[8] = {A0.x, A0.y, A0.z, A0.w, A1.x, A1.y, A1.z, A1.w};
            float4 bb = *(float4*)&Bs[kk][tx * 4];
            float bv[4] = {bb.x, bb.y, bb.z, bb.w};
            #pragma unroll
            for (int mi = 0; mi < 8; mi++)
                #pragma unroll
                for (int ni = 0; ni < 4; ni++)
                    c[mi][ni] += a[mi] * bv[ni];
        }
        __syncthreads();
    }

    #pragma unroll
    for (int mi = 0; mi < 8; mi++) {
        int r = ty * 8 + mi;
        int gr = m0 + r;
        float wrow = d_bucket_w[e * NTOK + gr];
        float* pp = d_partial + ((size_t)e * NTOK + gr) * DDIM + n0;
        #pragma unroll
        for (int ni = 0; ni < 4; ni++)
            pp[tx * 4 + ni] = c[mi][ni] * wrow;
    }
}

// ---------------------------------------------------------------------------
// Pass 3: out[n] = sum over active experts of partial rows. Deterministic.
// ---------------------------------------------------------------------------
__global__ __launch_bounds__(128) void gather_out(float* __restrict__ out)
{
    int n = blockIdx.x;
    int tid = threadIdx.x;
    float acc[4] = {0.f, 0.f, 0.f, 0.f};
    #pragma unroll
    for (int e = 0; e < ENUM; e++) {
        int s = d_slot[n * ENUM + e];
        if (s >= 0) {
            const float* pp = d_partial + ((size_t)e * NTOK + s) * DDIM;
            #pragma unroll
            for (int q = 0; q < 4; q++) acc[q] += pp[tid + q * 128];
        }
    }
    #pragma unroll
    for (int q = 0; q < 4; q++) out[(size_t)n * DDIM + tid + q * 128] = acc[q];
}

// ---------------------------------------------------------------------------
extern "C" void kernel_launch(void* const* d_in, const int* in_sizes, int n_in,
                              void* d_out, int out_size)
{
    const float* x  = (const float*)d_in[0];
    const float* Wr = (const float*)d_in[1];
    const float* br = (const float*)d_in[2];
    const float* Wg = (const float*)d_in[3];
    const float* bg = (const float*)d_in[4];
    const float* W1 = (const float*)d_in[5];
    const float* W3 = (const float*)d_in[6];
    const float* W2 = (const float*)d_in[7];
    float* out = (float*)d_out;

    routing_kernel<<<NTOK / 8, 256>>>(x, Wr, br, Wg, bg);
    build_buckets<<<ENUM, 256>>>();
    ffn_up<<<dim3(HDIM / TN, NTOK / TM, ENUM), 256>>>(x, W1, W3);
    ffn_down<<<dim3(DDIM / TN, NTOK / TM, ENUM), 256>>>(W2);
    gather_out<<<NTOK, 128>>>(out);
}